// round 7
// baseline (speedup 1.0000x reference)
#include <cuda_runtime.h>
#include <math_constants.h>
#include <cstdint>

// Problem constants (hardcoded shapes from reference)
#define KCODES 2048
#define DDIM   256
#define NROWS  65536   // B*T = 8*8192
#define BM     128     // rows per CTA
#define BN     128     // codes per K-tile
#define DC     128     // d-chunk per E smem load
#define EPSV   1e-5f

// Device scratch (no allocations allowed) : embed (K x D) and 0.5*||e||^2
__device__ float g_embed[KCODES * DDIM];
__device__ float g_bias[KCODES];

// ---------------------------------------------------------------------------
// Prep: embed = embed_sum / max(usage, eps);  g_bias = 0.5 * sum(embed^2)
// grid = KCODES, block = 64 (each thread: one float4 of the 256-d row)
// ---------------------------------------------------------------------------
__global__ void prep_kernel(const float* __restrict__ embed_sum,
                            const float* __restrict__ usage) {
    int k = blockIdx.x;
    int t = threadIdx.x;  // 0..63
    float inv = 1.0f / fmaxf(usage[k], EPSV);
    const float4* src = reinterpret_cast<const float4*>(embed_sum) + (size_t)k * 64;
    float4*       dst = reinterpret_cast<float4*>(g_embed) + (size_t)k * 64;
    float4 v = src[t];
    v.x *= inv; v.y *= inv; v.z *= inv; v.w *= inv;
    dst[t] = v;
    float s = v.x * v.x + v.y * v.y + v.z * v.z + v.w * v.w;
    #pragma unroll
    for (int m = 16; m > 0; m >>= 1) s += __shfl_xor_sync(0xffffffffu, s, m);
    __shared__ float ws[2];
    if ((t & 31) == 0) ws[t >> 5] = s;
    __syncthreads();
    if (t == 0) g_bias[k] = 0.5f * (ws[0] + ws[1]);
}

// Packed fp32x2 FMA (FFMA2) — PTX-only form, 2x FFMA throughput.
// Output constraint keeps it live; no 'volatile' so ptxas can schedule freely.
#define FMA2(accv, av, bv) \
    asm("fma.rn.f32x2 %0, %1, %2, %0;" : "+l"(accv) : "l"(av), "l"(bv))

// ---------------------------------------------------------------------------
// Main fused kernel: distances + argmin + gather
// grid = NROWS/BM = 512, block = 256 (16 ty x 16 tx), micro-tile 8x8
// smem: Xs [128 rows][64 granules of 16B] (swizzled)  = 128 KB
//       Es [128 codes][32 granules of 16B] (swizzled) =  64 KB
//       e2s[128], sidx[128]
// ---------------------------------------------------------------------------
__global__ __launch_bounds__(256, 1)
void vq_argmin_kernel(const float* __restrict__ X,
                      float* __restrict__ oInd,
                      float* __restrict__ oQ) {
    extern __shared__ unsigned char smem_raw[];
    ulonglong2* Xs  = reinterpret_cast<ulonglong2*>(smem_raw);            // [128*64]
    ulonglong2* Es  = Xs + BM * 64;                                       // [128*32]
    float*      e2s = reinterpret_cast<float*>(Es + BN * 32);             // [128]
    int*        sidx = reinterpret_cast<int*>(e2s + BN);                  // [128]

    const int tid = threadIdx.x;
    const int ty = tid >> 4;     // 0..15 : row group (8 rows each)
    const int tx = tid & 15;     // 0..15 : code group (8 codes each)
    const int row0 = blockIdx.x * BM;

    // ---- Load X tile (coalesced) into swizzled smem: phys granule = g ^ (row>>3)
    {
        const float4* src = reinterpret_cast<const float4*>(X) + (size_t)row0 * 64;
        const int sub = tid >> 6;   // 0..3
        const int g   = tid & 63;   // granule within row
        #pragma unroll
        for (int p = 0; p < 32; ++p) {
            int r = p * 4 + sub;
            float4 v = src[(size_t)r * 64 + g];
            int gp = g ^ (r >> 3);                 // (r>>3) in 0..15, XOR low 4 bits
            reinterpret_cast<float4*>(Xs)[r * 64 + gp] = v;
        }
    }

    float bestV[8];
    int   bestI[8];
    #pragma unroll
    for (int i = 0; i < 8; ++i) { bestV[i] = CUDART_INF_F; bestI[i] = 0; }

    unsigned long long acc[8][8];
    const ulonglong2* Xbase = Xs + (ty * 8) * 64;

    for (int kt = 0; kt < KCODES / BN; ++kt) {
        #pragma unroll
        for (int i = 0; i < 8; ++i)
            #pragma unroll
            for (int j = 0; j < 8; ++j) acc[i][j] = 0ULL;

        #pragma unroll
        for (int dc = 0; dc < DDIM / DC; ++dc) {
            __syncthreads();   // previous compute / epilogue reads done before overwriting Es
            // ---- Load E chunk (coalesced): codes kt*BN..+127, d in [dc*128, +128)
            {
                const float4* esrc = reinterpret_cast<const float4*>(g_embed)
                                     + (size_t)(kt * BN) * 64 + dc * 32;
                const int cbase = tid >> 5;   // 0..7
                const int g = tid & 31;       // granule within chunk row
                #pragma unroll
                for (int p = 0; p < 16; ++p) {
                    int cc = p * 8 + cbase;
                    float4 v = esrc[(size_t)cc * 64 + g];
                    int gp = g ^ (cc >> 3);        // key = code>>3 (0..15)
                    reinterpret_cast<float4*>(Es)[cc * 32 + gp] = v;
                }
                if (dc == 0 && tid < BN) e2s[tid] = g_bias[kt * BN + tid];
            }
            __syncthreads();

            // ---- Compute: 128 d per chunk, 4 d per step (one 16B granule)
            const int xg0 = dc * 32;
            #pragma unroll 1
            for (int gg = 0; gg < 32; ++gg) {
                ulonglong2 xv[8];
                #pragma unroll
                for (int i = 0; i < 8; ++i)
                    xv[i] = Xbase[i * 64 + ((xg0 + gg) ^ ty)];
                ulonglong2 ev[8];
                #pragma unroll
                for (int j = 0; j < 8; ++j)
                    ev[j] = Es[(tx * 8 + j) * 32 + (gg ^ tx)];
                #pragma unroll
                for (int i = 0; i < 8; ++i)
                    #pragma unroll
                    for (int j = 0; j < 8; ++j) {
                        FMA2(acc[i][j], xv[i].x, ev[j].x);
                        FMA2(acc[i][j], xv[i].y, ev[j].y);
                    }
            }
        }

        // ---- Epilogue for this code tile: score = 0.5|e|^2 - x.e ; argmin
        #pragma unroll
        for (int i = 0; i < 8; ++i) {
            #pragma unroll
            for (int j = 0; j < 8; ++j) {
                float lo, hi;
                asm("mov.b64 {%0,%1}, %2;" : "=f"(lo), "=f"(hi) : "l"(acc[i][j]));
                float score = e2s[tx * 8 + j] - (lo + hi);
                int c = kt * BN + tx * 8 + j;
                if (score < bestV[i]) { bestV[i] = score; bestI[i] = c; }
            }
        }
    }

    // ---- Reduce argmin across the 16 tx lanes sharing the same rows (half-warp)
    #pragma unroll
    for (int i = 0; i < 8; ++i) {
        float v = bestV[i]; int b = bestI[i];
        #pragma unroll
        for (int m = 8; m > 0; m >>= 1) {
            float ov = __shfl_xor_sync(0xffffffffu, v, m);
            int   ob = __shfl_xor_sync(0xffffffffu, b, m);
            if (ov < v || (ov == v && ob < b)) { v = ov; b = ob; }
        }
        if (tx == 0) sidx[ty * 8 + i] = b;
    }
    __syncthreads();

    // ---- Write indices (as float) and gather quantized rows (coalesced)
    if (oInd != nullptr && tid < BM) oInd[row0 + tid] = (float)sidx[tid];
    if (oQ != nullptr) {
        const int sub = tid >> 6;
        const int g   = tid & 63;
        float4* dst = reinterpret_cast<float4*>(oQ) + (size_t)row0 * 64;
        const float4* emb = reinterpret_cast<const float4*>(g_embed);
        #pragma unroll
        for (int p = 0; p < 32; ++p) {
            int r = p * 4 + sub;
            dst[(size_t)r * 64 + g] = emb[(size_t)sidx[r] * 64 + g];
        }
    }
}

// ---------------------------------------------------------------------------
extern "C" void kernel_launch(void* const* d_in, const int* in_sizes, int n_in,
                              void* d_out, int out_size) {
    // Identify inputs by element count (robust to ordering)
    const float* X  = nullptr;   // 65536*256
    const float* ES = nullptr;   // 2048*256
    const float* CU = nullptr;   // 2048
    for (int i = 0; i < n_in; ++i) {
        if (in_sizes[i] == NROWS * DDIM)       X  = (const float*)d_in[i];
        else if (in_sizes[i] == KCODES * DDIM) ES = (const float*)d_in[i];
        else if (in_sizes[i] == KCODES)        CU = (const float*)d_in[i];
    }

    // Output layout: tuple (embed_ind, quantized) concatenated as float32
    float* out = (float*)d_out;
    float* oInd = nullptr;
    float* oQ   = nullptr;
    const long long NI = NROWS;                   // 65536 indices
    const long long NQ = (long long)NROWS * DDIM; // 16777216 quantized
    if ((long long)out_size >= NI + NQ) { oInd = out; oQ = out + NI; }
    else if ((long long)out_size >= NQ) { oQ = out; }
    else                                { oInd = out; }

    const size_t SMEM_BYTES = (size_t)BM * 64 * 16   // Xs 128KB
                            + (size_t)BN * 32 * 16   // Es  64KB
                            + BN * sizeof(float)     // e2s
                            + BM * sizeof(int);      // sidx
    cudaFuncSetAttribute(vq_argmin_kernel,
                         cudaFuncAttributeMaxDynamicSharedMemorySize,
                         (int)SMEM_BYTES);

    prep_kernel<<<KCODES, 64>>>(ES, CU);
    vq_argmin_kernel<<<NROWS / BM, 256, SMEM_BYTES>>>(X, oInd, oQ);
}

// round 13
// speedup vs baseline: 1.3708x; 1.3708x over previous
#include <cuda_runtime.h>
#include <cuda_bf16.h>
#include <math_constants.h>
#include <cstdint>

#define KCODES 2048
#define DDIM   256
#define NROWS  65536
#define BM     64
#define EPSV   1e-5f

// SMEM layout (bytes)
#define XS_OFF     0         // 3 terms x 64 rows x 512B = 98304
#define ES_OFF     98304     // 2 bufs x 3 terms x 32 codes x 512B = 98304
#define BIAS_OFF   196608    // 2048 f32 = 8192
#define CANDV_OFF  204800    // 2 x 64 f32
#define CANDI_OFF  205312    // 2 x 64 i32
#define SIDX_OFF   205824    // 64 i32
#define SMEM_TOTAL 206080

// Device scratch
__device__ float g_embed[KCODES * DDIM];
__device__ float g_bias[KCODES];
__device__ __nv_bfloat16 g_ehi[KCODES * DDIM];
__device__ __nv_bfloat16 g_emid[KCODES * DDIM];
__device__ __nv_bfloat16 g_elo[KCODES * DDIM];

// ---------------- PTX helpers (all base-arch instructions, sm_80+) ----------
__device__ __forceinline__ uint32_t smem_u32(const void* p) {
    uint32_t a;
    asm("{ .reg .u64 t; cvta.to.shared.u64 t, %1; cvt.u32.u64 %0, t; }" : "=r"(a) : "l"(p));
    return a;
}
#define LDSM_X4(r, addr) \
    asm volatile("ldmatrix.sync.aligned.m8n8.x4.shared.b16 {%0,%1,%2,%3}, [%4];" \
        : "=r"((r)[0]), "=r"((r)[1]), "=r"((r)[2]), "=r"((r)[3]) : "r"(addr))
#define MMA_BF16(d, a, b0, b1) \
    asm volatile("mma.sync.aligned.m16n8k16.row.col.f32.bf16.bf16.f32 " \
        "{%0,%1,%2,%3}, {%4,%5,%6,%7}, {%8,%9}, {%0,%1,%2,%3};" \
        : "+f"((d)[0]), "+f"((d)[1]), "+f"((d)[2]), "+f"((d)[3]) \
        : "r"((a)[0]), "r"((a)[1]), "r"((a)[2]), "r"((a)[3]), "r"(b0), "r"(b1))
#define CP_ASYNC16(dst, src) \
    asm volatile("cp.async.ca.shared.global [%0], [%1], 16;" :: "r"(dst), "l"(src))
#define CP_COMMIT() asm volatile("cp.async.commit_group;" ::: "memory")
#define CP_WAIT0()  asm volatile("cp.async.wait_group 0;" ::: "memory")
#define CP_WAIT1()  asm volatile("cp.async.wait_group 1;" ::: "memory")

// ---------------------------------------------------------------------------
// Prep: embed = embed_sum/max(usage,eps); bias = 0.5|e|^2; 3-term bf16 split
// ---------------------------------------------------------------------------
__global__ void prep_kernel(const float* __restrict__ embed_sum,
                            const float* __restrict__ usage) {
    int k = blockIdx.x, t = threadIdx.x;   // t: 0..63, one float4 each
    float inv = 1.0f / fmaxf(usage[k], EPSV);
    float4 v = reinterpret_cast<const float4*>(embed_sum)[(size_t)k * 64 + t];
    v.x *= inv; v.y *= inv; v.z *= inv; v.w *= inv;
    reinterpret_cast<float4*>(g_embed)[(size_t)k * 64 + t] = v;

    float e[4] = {v.x, v.y, v.z, v.w};
    unsigned short hh[4], mm[4], ll[4];
    #pragma unroll
    for (int j = 0; j < 4; ++j) {
        __nv_bfloat16 h = __float2bfloat16_rn(e[j]);
        float r = e[j] - __bfloat162float(h);
        __nv_bfloat16 m = __float2bfloat16_rn(r);
        float r2 = r - __bfloat162float(m);
        __nv_bfloat16 l = __float2bfloat16_rn(r2);
        hh[j] = *reinterpret_cast<unsigned short*>(&h);
        mm[j] = *reinterpret_cast<unsigned short*>(&m);
        ll[j] = *reinterpret_cast<unsigned short*>(&l);
    }
    uint2 uh, um, ul;
    uh.x = (uint32_t)hh[0] | ((uint32_t)hh[1] << 16); uh.y = (uint32_t)hh[2] | ((uint32_t)hh[3] << 16);
    um.x = (uint32_t)mm[0] | ((uint32_t)mm[1] << 16); um.y = (uint32_t)mm[2] | ((uint32_t)mm[3] << 16);
    ul.x = (uint32_t)ll[0] | ((uint32_t)ll[1] << 16); ul.y = (uint32_t)ll[2] | ((uint32_t)ll[3] << 16);
    reinterpret_cast<uint2*>(g_ehi)[(size_t)k * 64 + t]  = uh;
    reinterpret_cast<uint2*>(g_emid)[(size_t)k * 64 + t] = um;
    reinterpret_cast<uint2*>(g_elo)[(size_t)k * 64 + t]  = ul;

    float s = v.x * v.x + v.y * v.y + v.z * v.z + v.w * v.w;
    #pragma unroll
    for (int m2 = 16; m2 > 0; m2 >>= 1) s += __shfl_xor_sync(0xffffffffu, s, m2);
    __shared__ float ws[2];
    if ((t & 31) == 0) ws[t >> 5] = s;
    __syncthreads();
    if (t == 0) g_bias[k] = 0.5f * (ws[0] + ws[1]);
}

// Fill one E tile (32 codes) x 3 terms into buffer b via cp.async.
// Per thread 12 granules of 16B; warp = one code row -> coalesced 512B.
__device__ __forceinline__ void fill_etile(uint32_t sb, int tid, int tile, int b) {
    const __nv_bfloat16* terms[3] = {g_ehi, g_emid, g_elo};
    #pragma unroll
    for (int it = 0; it < 12; ++it) {
        int idx = it * 256 + tid;
        int term = idx >> 10;
        int rem  = idx & 1023;
        int code = rem >> 5;
        int g    = rem & 31;
        const __nv_bfloat16* src = terms[term] + ((size_t)(tile * 32 + code) * DDIM + g * 8);
        uint32_t dst = sb + ES_OFF + (uint32_t)(b * 49152 + term * 16384 + code * 512
                     + ((g * 16) ^ ((code & 7) << 4)));
        CP_ASYNC16(dst, src);
    }
}

// ---------------------------------------------------------------------------
// Main: warp-level bf16 HMMA (mma.sync m16n8k16) 3-term split GEMM + argmin
// grid = 1024, block = 256 (8 warps = 4 row-groups x 2 code-groups)
// ---------------------------------------------------------------------------
__global__ __launch_bounds__(256, 1)
void vq_mma_kernel(const float* __restrict__ X,
                   float* __restrict__ oInd,
                   float* __restrict__ oQ) {
    extern __shared__ unsigned char smem[];
    uint32_t sb = smem_u32(smem);
    float* bias_s = reinterpret_cast<float*>(smem + BIAS_OFF);
    float* candV  = reinterpret_cast<float*>(smem + CANDV_OFF);
    int*   candI  = reinterpret_cast<int*>(smem + CANDI_OFF);
    int*   sidx_s = reinterpret_cast<int*>(smem + SIDX_OFF);

    const int tid  = threadIdx.x;
    const int wid  = tid >> 5;
    const int lane = tid & 31;
    const int rg   = wid & 3;        // row group: rows rg*16..+15
    const int cg   = wid >> 2;       // code group: 16 of 32 codes per tile
    const int row0 = blockIdx.x * BM;

    // bias -> smem
    #pragma unroll
    for (int i = tid; i < KCODES; i += 256) bias_s[i] = g_bias[i];

    // X tile -> 3 bf16 terms in smem (row-major 512B rows, granule swizzle)
    {
        int row = tid >> 2;                  // 0..63
        int cb  = (tid & 3) * 64;            // dim base
        const float2* xr = reinterpret_cast<const float2*>(X + (size_t)(row0 + row) * DDIM);
        #pragma unroll
        for (int i = 0; i < 32; ++i) {
            int d0 = cb + i * 2;
            float2 v = xr[d0 >> 1];
            uint32_t cbyte = (uint32_t)(d0 * 2) ^ ((row & 7) << 4);
            float a = v.x, bv = v.y;
            #pragma unroll
            for (int t = 0; t < 3; ++t) {
                __nv_bfloat16 ha = __float2bfloat16_rn(a), hb = __float2bfloat16_rn(bv);
                uint32_t lo16 = *reinterpret_cast<unsigned short*>(&ha);
                uint32_t hi16 = *reinterpret_cast<unsigned short*>(&hb);
                *reinterpret_cast<uint32_t*>(smem + XS_OFF + t * 32768 + row * 512 + cbyte)
                    = lo16 | (hi16 << 16);
                a  -= __bfloat162float(ha);
                bv -= __bfloat162float(hb);
            }
        }
    }

    // ldmatrix per-lane geometry (same for A and B)
    const int frow = ((lane >> 3) & 1) * 8 + (lane & 7);  // 0..15 row within 16
    const int kofs = (lane >> 4) * 16;                    // byte offset within k16

    const int arow = rg * 16 + frow;                      // X row
    const uint32_t aswz = (uint32_t)((arow & 7) << 4);
    const uint32_t abase = sb + XS_OFF + (uint32_t)(arow * 512);

    const int brow = cg * 16 + frow;                      // code within 32-tile
    const uint32_t bswz = (uint32_t)((brow & 7) << 4);
    const uint32_t bbase = sb + ES_OFF + (uint32_t)(brow * 512);

    float bestV0 = CUDART_INF_F, bestV1 = CUDART_INF_F;
    int   bestI0 = 0,            bestI1 = 0;
    const int r0lane = lane >> 2;        // 0..7
    const int n0lane = 2 * (lane & 3);   // 0,2,4,6

    // preload first E tile
    fill_etile(sb, tid, 0, 0);
    CP_COMMIT();

    for (int t = 0; t < 64; ++t) {
        if (t < 63) { fill_etile(sb, tid, t + 1, (t + 1) & 1); CP_COMMIT(); CP_WAIT1(); }
        else        { CP_WAIT0(); }
        __syncthreads();

        const uint32_t ebuf = bbase + (uint32_t)((t & 1) * 49152);
        float d0[4] = {0.f, 0.f, 0.f, 0.f};   // n8 tile 0 (codes cb..cb+7)
        float d1[4] = {0.f, 0.f, 0.f, 0.f};   // n8 tile 1 (codes cb+8..15)

        #pragma unroll
        for (int ks = 0; ks < 16; ++ks) {
            uint32_t koff = (uint32_t)(ks * 32 + kofs);
            uint32_t af[3][4], bf[3][4];
            #pragma unroll
            for (int tm = 0; tm < 3; ++tm) {
                LDSM_X4(af[tm], abase + (uint32_t)(tm * 32768) + (koff ^ aswz));
                LDSM_X4(bf[tm], ebuf  + (uint32_t)(tm * 16384) + (koff ^ bswz));
            }
            // products: hh, hM, mH, hL, lH, mM   (b regs {0,2}=tile0, {1,3}=tile1)
            MMA_BF16(d0, af[0], bf[0][0], bf[0][2]);  MMA_BF16(d1, af[0], bf[0][1], bf[0][3]);
            MMA_BF16(d0, af[0], bf[1][0], bf[1][2]);  MMA_BF16(d1, af[0], bf[1][1], bf[1][3]);
            MMA_BF16(d0, af[1], bf[0][0], bf[0][2]);  MMA_BF16(d1, af[1], bf[0][1], bf[0][3]);
            MMA_BF16(d0, af[0], bf[2][0], bf[2][2]);  MMA_BF16(d1, af[0], bf[2][1], bf[2][3]);
            MMA_BF16(d0, af[2], bf[0][0], bf[0][2]);  MMA_BF16(d1, af[2], bf[0][1], bf[0][3]);
            MMA_BF16(d0, af[1], bf[1][0], bf[1][2]);  MMA_BF16(d1, af[1], bf[1][1], bf[1][3]);
        }

        // epilogue: score = 0.5|e|^2 - dot ; running per-lane argmin
        int cb = t * 32 + cg * 16;
        #pragma unroll
        for (int nt = 0; nt < 2; ++nt) {
            const float* dd = nt ? d1 : d0;
            int c0 = cb + nt * 8 + n0lane;
            float s0 = bias_s[c0]     - dd[0];
            float s1 = bias_s[c0 + 1] - dd[1];
            float s2 = bias_s[c0]     - dd[2];
            float s3 = bias_s[c0 + 1] - dd[3];
            if (s0 < bestV0) { bestV0 = s0; bestI0 = c0; }
            if (s1 < bestV0) { bestV0 = s1; bestI0 = c0 + 1; }
            if (s2 < bestV1) { bestV1 = s2; bestI1 = c0; }
            if (s3 < bestV1) { bestV1 = s3; bestI1 = c0 + 1; }
        }
        __syncthreads();   // all warps done reading buf before next fill reuses it
    }

    // reduce argmin across the 4 lanes sharing each row
    #pragma unroll
    for (int m = 1; m <= 2; m <<= 1) {
        float ov = __shfl_xor_sync(0xffffffffu, bestV0, m);
        int   ob = __shfl_xor_sync(0xffffffffu, bestI0, m);
        if (ov < bestV0 || (ov == bestV0 && ob < bestI0)) { bestV0 = ov; bestI0 = ob; }
        ov = __shfl_xor_sync(0xffffffffu, bestV1, m);
        ob = __shfl_xor_sync(0xffffffffu, bestI1, m);
        if (ov < bestV1 || (ov == bestV1 && ob < bestI1)) { bestV1 = ov; bestI1 = ob; }
    }
    if ((lane & 3) == 0) {
        int rA = rg * 16 + r0lane;
        candV[cg * 64 + rA] = bestV0;  candI[cg * 64 + rA] = bestI0;
        candV[cg * 64 + rA + 8] = bestV1;  candI[cg * 64 + rA + 8] = bestI1;
    }
    __syncthreads();

    if (tid < BM) {
        float vA = candV[tid], vB = candV[64 + tid];
        int   iA = candI[tid], iB = candI[64 + tid];
        int best = (vB < vA || (vB == vA && iB < iA)) ? iB : iA;
        sidx_s[tid] = best;
        if (oInd != nullptr) oInd[row0 + tid] = (float)best;
    }
    __syncthreads();

    if (oQ != nullptr) {
        float4* dst = reinterpret_cast<float4*>(oQ) + (size_t)row0 * 64;
        const float4* emb = reinterpret_cast<const float4*>(g_embed);
        #pragma unroll
        for (int p = 0; p < 16; ++p) {
            int idx = p * 256 + tid;
            int r = idx >> 6, g = idx & 63;
            dst[(size_t)r * 64 + g] = emb[(size_t)sidx_s[r] * 64 + g];
        }
    }
}

// ---------------------------------------------------------------------------
extern "C" void kernel_launch(void* const* d_in, const int* in_sizes, int n_in,
                              void* d_out, int out_size) {
    const float* X  = nullptr;
    const float* ES = nullptr;
    const float* CU = nullptr;
    for (int i = 0; i < n_in; ++i) {
        if (in_sizes[i] == NROWS * DDIM)       X  = (const float*)d_in[i];
        else if (in_sizes[i] == KCODES * DDIM) ES = (const float*)d_in[i];
        else if (in_sizes[i] == KCODES)        CU = (const float*)d_in[i];
    }

    float* out = (float*)d_out;
    float* oInd = nullptr;
    float* oQ   = nullptr;
    const long long NI = NROWS;
    const long long NQ = (long long)NROWS * DDIM;
    if ((long long)out_size >= NI + NQ) { oInd = out; oQ = out + NI; }
    else if ((long long)out_size >= NQ) { oQ = out; }
    else                                { oInd = out; }

    cudaFuncSetAttribute(vq_mma_kernel,
                         cudaFuncAttributeMaxDynamicSharedMemorySize, SMEM_TOTAL);

    prep_kernel<<<KCODES, 64>>>(ES, CU);
    vq_mma_kernel<<<NROWS / BM, 256, SMEM_TOTAL>>>(X, oInd, oQ);
}

// round 15
// speedup vs baseline: 1.9712x; 1.4380x over previous
#include <cuda_runtime.h>
#include <cuda_fp16.h>
#include <math_constants.h>
#include <cstdint>

#define KCODES 2048
#define DDIM   256
#define NROWS  65536
#define BM     128
#define EPSV   1e-5f

// SMEM layout (bytes)
#define XS_OFF     0         // 2 terms x 128 rows x 512B = 131072
#define ES_OFF     131072    // 2 bufs x 2 terms x 32 codes x 512B = 65536
#define BIAS_OFF   196608    // 2048 f32 = 8192
#define SIDX_OFF   204800    // 128 i32
#define SMEM_TOTAL 205312

// Device scratch
__device__ float g_embed[KCODES * DDIM];
__device__ float g_bias[KCODES];
__device__ __half g_ehi[KCODES * DDIM];
__device__ __half g_emid[KCODES * DDIM];

// ---------------- PTX helpers (base-arch, sm_80+) ---------------------------
__device__ __forceinline__ uint32_t smem_u32(const void* p) {
    uint32_t a;
    asm("{ .reg .u64 t; cvta.to.shared.u64 t, %1; cvt.u32.u64 %0, t; }" : "=r"(a) : "l"(p));
    return a;
}
#define LDSM_X4(r, addr) \
    asm volatile("ldmatrix.sync.aligned.m8n8.x4.shared.b16 {%0,%1,%2,%3}, [%4];" \
        : "=r"((r)[0]), "=r"((r)[1]), "=r"((r)[2]), "=r"((r)[3]) : "r"(addr))
#define MMA_F16(d, a, b0, b1) \
    asm volatile("mma.sync.aligned.m16n8k16.row.col.f32.f16.f16.f32 " \
        "{%0,%1,%2,%3}, {%4,%5,%6,%7}, {%8,%9}, {%0,%1,%2,%3};" \
        : "+f"((d)[0]), "+f"((d)[1]), "+f"((d)[2]), "+f"((d)[3]) \
        : "r"((a)[0]), "r"((a)[1]), "r"((a)[2]), "r"((a)[3]), "r"(b0), "r"(b1))
#define CP_ASYNC16(dst, src) \
    asm volatile("cp.async.ca.shared.global [%0], [%1], 16;" :: "r"(dst), "l"(src))
#define CP_COMMIT() asm volatile("cp.async.commit_group;" ::: "memory")
#define CP_WAIT0()  asm volatile("cp.async.wait_group 0;" ::: "memory")
#define CP_WAIT1()  asm volatile("cp.async.wait_group 1;" ::: "memory")

// ---------------------------------------------------------------------------
// Prep: embed = embed_sum/max(usage,eps); bias = 0.5|e|^2; 2-term fp16 split
// ---------------------------------------------------------------------------
__global__ void prep_kernel(const float* __restrict__ embed_sum,
                            const float* __restrict__ usage) {
    int k = blockIdx.x, t = threadIdx.x;   // t: 0..63, one float4 each
    float inv = 1.0f / fmaxf(usage[k], EPSV);
    float4 v = reinterpret_cast<const float4*>(embed_sum)[(size_t)k * 64 + t];
    v.x *= inv; v.y *= inv; v.z *= inv; v.w *= inv;
    reinterpret_cast<float4*>(g_embed)[(size_t)k * 64 + t] = v;

    float e[4] = {v.x, v.y, v.z, v.w};
    unsigned short hh[4], mm[4];
    #pragma unroll
    for (int j = 0; j < 4; ++j) {
        __half h = __float2half_rn(e[j]);
        float r = e[j] - __half2float(h);
        __half m = __float2half_rn(r);
        hh[j] = *reinterpret_cast<unsigned short*>(&h);
        mm[j] = *reinterpret_cast<unsigned short*>(&m);
    }
    uint2 uh, um;
    uh.x = (uint32_t)hh[0] | ((uint32_t)hh[1] << 16); uh.y = (uint32_t)hh[2] | ((uint32_t)hh[3] << 16);
    um.x = (uint32_t)mm[0] | ((uint32_t)mm[1] << 16); um.y = (uint32_t)mm[2] | ((uint32_t)mm[3] << 16);
    reinterpret_cast<uint2*>(g_ehi)[(size_t)k * 64 + t]  = uh;
    reinterpret_cast<uint2*>(g_emid)[(size_t)k * 64 + t] = um;

    float s = v.x * v.x + v.y * v.y + v.z * v.z + v.w * v.w;
    #pragma unroll
    for (int m2 = 16; m2 > 0; m2 >>= 1) s += __shfl_xor_sync(0xffffffffu, s, m2);
    __shared__ float ws[2];
    if ((t & 31) == 0) ws[t >> 5] = s;
    __syncthreads();
    if (t == 0) g_bias[k] = 0.5f * (ws[0] + ws[1]);
}

// Fill one E tile (32 codes) x 2 terms into buffer b: 8 cp.async granules/thread
__device__ __forceinline__ void fill_etile(uint32_t sb, int tid, int tile, int b) {
    #pragma unroll
    for (int it = 0; it < 8; ++it) {
        int idx = it * 256 + tid;
        int term = idx >> 10;                  // 0..1
        int rem  = idx & 1023;
        int code = rem >> 5;                   // 0..31
        int g    = rem & 31;                   // 16B granule within 512B row
        const __half* src = (term ? g_emid : g_ehi)
                          + ((size_t)(tile * 32 + code) * DDIM + g * 8);
        uint32_t dst = sb + ES_OFF + (uint32_t)(b * 32768 + term * 16384 + code * 512
                     + ((g * 16) ^ ((code & 7) << 4)));
        CP_ASYNC16(dst, src);
    }
}

// ---------------------------------------------------------------------------
// Main: fp16 2-term split (4 products), A-frags register-resident.
// grid = 512, block = 256. Warp w owns rows w*16..+15 x all 32 codes/tile.
// ---------------------------------------------------------------------------
__global__ __launch_bounds__(256, 1)
void vq_mma_kernel(const float* __restrict__ X,
                   float* __restrict__ oInd,
                   float* __restrict__ oQ) {
    extern __shared__ unsigned char smem[];
    uint32_t sb = smem_u32(smem);
    float* bias_s = reinterpret_cast<float*>(smem + BIAS_OFF);
    int*   sidx_s = reinterpret_cast<int*>(smem + SIDX_OFF);

    const int tid  = threadIdx.x;
    const int wid  = tid >> 5;
    const int lane = tid & 31;
    const int row0 = blockIdx.x * BM;

    // bias -> smem
    #pragma unroll
    for (int i = tid; i < KCODES; i += 256) bias_s[i] = g_bias[i];

    // X tile -> 2 fp16 terms in smem (512B rows, 16B-granule swizzle)
    {
        int row = tid >> 1;                  // 0..127
        int cb  = (tid & 1) * 128;           // dim base
        const float2* xr = reinterpret_cast<const float2*>(X + (size_t)(row0 + row) * DDIM);
        #pragma unroll
        for (int i = 0; i < 64; ++i) {
            int d0 = cb + i * 2;
            float2 v = xr[d0 >> 1];
            uint32_t cbyte = (uint32_t)(d0 * 2) ^ ((row & 7) << 4);
            __half ha = __float2half_rn(v.x), hb = __float2half_rn(v.y);
            uint32_t lo = *reinterpret_cast<unsigned short*>(&ha);
            uint32_t hi = *reinterpret_cast<unsigned short*>(&hb);
            *reinterpret_cast<uint32_t*>(smem + XS_OFF + row * 512 + cbyte) = lo | (hi << 16);
            __half ma = __float2half_rn(v.x - __half2float(ha));
            __half mb = __float2half_rn(v.y - __half2float(hb));
            lo = *reinterpret_cast<unsigned short*>(&ma);
            hi = *reinterpret_cast<unsigned short*>(&mb);
            *reinterpret_cast<uint32_t*>(smem + XS_OFF + 65536 + row * 512 + cbyte) = lo | (hi << 16);
        }
    }

    // kick off first E tile while X stores settle
    fill_etile(sb, tid, 0, 0);
    CP_COMMIT();
    __syncthreads();

    // ldmatrix lane geometry
    const int frow = ((lane >> 3) & 1) * 8 + (lane & 7);  // 0..15
    const int kofs = (lane >> 4) * 16;

    // A fragments (X rows wid*16..+15), ALL k-steps, both terms -> registers
    const int arow = wid * 16 + frow;
    const uint32_t aswz  = (uint32_t)((arow & 7) << 4);
    const uint32_t abase = sb + XS_OFF + (uint32_t)(arow * 512);
    uint32_t aA[2][16][4];
    #pragma unroll
    for (int t = 0; t < 2; ++t)
        #pragma unroll
        for (int ks = 0; ks < 16; ++ks)
            LDSM_X4(aA[t][ks], abase + (uint32_t)(t * 65536) + ((uint32_t)(ks * 32 + kofs) ^ aswz));

    // B lane bases: two 16-code halves
    const int brow0 = frow, brow1 = 16 + frow;
    const uint32_t bs0 = (uint32_t)((brow0 & 7) << 4), bs1 = (uint32_t)((brow1 & 7) << 4);

    float bestV0 = CUDART_INF_F, bestV1 = CUDART_INF_F;
    int   bestI0 = 0,            bestI1 = 0;
    const int r0lane = lane >> 2;        // 0..7
    const int n0lane = 2 * (lane & 3);   // 0,2,4,6

    for (int t = 0; t < 64; ++t) {
        if (t < 63) { fill_etile(sb, tid, t + 1, (t + 1) & 1); CP_COMMIT(); CP_WAIT1(); }
        else        { CP_WAIT0(); }
        __syncthreads();

        const uint32_t ebuf = sb + ES_OFF + (uint32_t)((t & 1) * 32768);
        float d[4][4];
        #pragma unroll
        for (int j = 0; j < 4; ++j)
            #pragma unroll
            for (int q = 0; q < 4; ++q) d[j][q] = 0.f;

        #pragma unroll
        for (int ks = 0; ks < 16; ++ks) {
            uint32_t koff = (uint32_t)(ks * 32 + kofs);
            uint32_t bf[2][2][4];   // term x code-half x 4
            #pragma unroll
            for (int tb = 0; tb < 2; ++tb) {
                LDSM_X4(bf[tb][0], ebuf + (uint32_t)(tb * 16384 + brow0 * 512) + (koff ^ bs0));
                LDSM_X4(bf[tb][1], ebuf + (uint32_t)(tb * 16384 + brow1 * 512) + (koff ^ bs1));
            }
            // products: hh, hM, mH, mM ; n8-tiles j: 0..3 (codes j*8..j*8+7)
            #pragma unroll
            for (int ta = 0; ta < 2; ++ta)
                #pragma unroll
                for (int tb = 0; tb < 2; ++tb) {
                    MMA_F16(d[0], aA[ta][ks], bf[tb][0][0], bf[tb][0][2]);
                    MMA_F16(d[1], aA[ta][ks], bf[tb][0][1], bf[tb][0][3]);
                    MMA_F16(d[2], aA[ta][ks], bf[tb][1][0], bf[tb][1][2]);
                    MMA_F16(d[3], aA[ta][ks], bf[tb][1][1], bf[tb][1][3]);
                }
        }

        // epilogue: score = 0.5|e|^2 - dot ; running per-lane argmin
        #pragma unroll
        for (int j = 0; j < 4; ++j) {
            int c0 = t * 32 + j * 8 + n0lane;
            float s0 = bias_s[c0]     - d[j][0];   // row r0lane
            float s1 = bias_s[c0 + 1] - d[j][1];
            float s2 = bias_s[c0]     - d[j][2];   // row r0lane+8
            float s3 = bias_s[c0 + 1] - d[j][3];
            if (s0 < bestV0) { bestV0 = s0; bestI0 = c0; }
            if (s1 < bestV0) { bestV0 = s1; bestI0 = c0 + 1; }
            if (s2 < bestV1) { bestV1 = s2; bestI1 = c0; }
            if (s3 < bestV1) { bestV1 = s3; bestI1 = c0 + 1; }
        }
        __syncthreads();   // all warps done reading buf before next fill reuses it
    }

    // reduce argmin across the 4 lanes sharing each row (whole tile in-warp)
    #pragma unroll
    for (int m = 1; m <= 2; m <<= 1) {
        float ov = __shfl_xor_sync(0xffffffffu, bestV0, m);
        int   ob = __shfl_xor_sync(0xffffffffu, bestI0, m);
        if (ov < bestV0 || (ov == bestV0 && ob < bestI0)) { bestV0 = ov; bestI0 = ob; }
        ov = __shfl_xor_sync(0xffffffffu, bestV1, m);
        ob = __shfl_xor_sync(0xffffffffu, bestI1, m);
        if (ov < bestV1 || (ov == bestV1 && ob < bestI1)) { bestV1 = ov; bestI1 = ob; }
    }
    if ((lane & 3) == 0) {
        int rA = wid * 16 + r0lane;
        sidx_s[rA] = bestI0;
        sidx_s[rA + 8] = bestI1;
        if (oInd != nullptr) {
            oInd[row0 + rA] = (float)bestI0;
            oInd[row0 + rA + 8] = (float)bestI1;
        }
    }
    __syncthreads();

    if (oQ != nullptr) {
        float4* dst = reinterpret_cast<float4*>(oQ) + (size_t)row0 * 64;
        const float4* emb = reinterpret_cast<const float4*>(g_embed);
        #pragma unroll
        for (int p = 0; p < 32; ++p) {
            int idx = p * 256 + tid;
            int r = idx >> 6, g = idx & 63;
            dst[(size_t)r * 64 + g] = emb[(size_t)sidx_s[r] * 64 + g];
        }
    }
}

// ---------------------------------------------------------------------------
extern "C" void kernel_launch(void* const* d_in, const int* in_sizes, int n_in,
                              void* d_out, int out_size) {
    const float* X  = nullptr;
    const float* ES = nullptr;
    const float* CU = nullptr;
    for (int i = 0; i < n_in; ++i) {
        if (in_sizes[i] == NROWS * DDIM)       X  = (const float*)d_in[i];
        else if (in_sizes[i] == KCODES * DDIM) ES = (const float*)d_in[i];
        else if (in_sizes[i] == KCODES)        CU = (const float*)d_in[i];
    }

    float* out = (float*)d_out;
    float* oInd = nullptr;
    float* oQ   = nullptr;
    const long long NI = NROWS;
    const long long NQ = (long long)NROWS * DDIM;
    if ((long long)out_size >= NI + NQ) { oInd = out; oQ = out + NI; }
    else if ((long long)out_size >= NQ) { oQ = out; }
    else                                { oInd = out; }

    cudaFuncSetAttribute(vq_mma_kernel,
                         cudaFuncAttributeMaxDynamicSharedMemorySize, SMEM_TOTAL);

    prep_kernel<<<KCODES, 64>>>(ES, CU);
    vq_mma_kernel<<<NROWS / BM, 256, SMEM_TOTAL>>>(X, oInd, oQ);
}